// round 2
// baseline (speedup 1.0000x reference)
#include <cuda_runtime.h>
#include <stdint.h>

#define BATCH 4
#define SEQ   2048
#define DIM   1024
#define NH    16
#define HD    64
#define SCALE 0.125f
#define MTOT  (BATCH*SEQ)

// ---- scratch (no cudaMalloc allowed) ----
__device__ float g_q[MTOT * DIM];
__device__ float g_k[MTOT * DIM];
__device__ float g_v[MTOT * DIM];
__device__ float g_ctx[MTOT * DIM];
__device__ float g_r[(size_t)BATCH * SEQ * SEQ];  // 1/Z

// ---- helpers ----
__device__ __forceinline__ uint32_t f2tf(float x) {
    uint32_t u;
    asm("cvt.rna.tf32.f32 %0, %1;" : "=r"(u) : "f"(x));
    return u;
}
__device__ __forceinline__ uint32_t ldbits(const float* p) { return __float_as_uint(*p); }

__device__ __forceinline__ void mma8(float c[4], const uint32_t a[4], const uint32_t b[2]) {
    asm volatile(
        "mma.sync.aligned.m16n8k8.row.col.f32.tf32.tf32.f32 "
        "{%0,%1,%2,%3}, {%4,%5,%6,%7}, {%8,%9}, {%0,%1,%2,%3};\n"
        : "+f"(c[0]), "+f"(c[1]), "+f"(c[2]), "+f"(c[3])
        : "r"(a[0]), "r"(a[1]), "r"(a[2]), "r"(a[3]), "r"(b[0]), "r"(b[1]));
}

__device__ __forceinline__ void cpa16(float* s, const float* g) {
    uint32_t sa = (uint32_t)__cvta_generic_to_shared(s);
    asm volatile("cp.async.ca.shared.global [%0], [%1], 16;\n" ::"r"(sa), "l"(g));
}
__device__ __forceinline__ void cp_commit() { asm volatile("cp.async.commit_group;\n"); }
template <int N>
__device__ __forceinline__ void cp_wait() { asm volatile("cp.async.wait_group %0;\n" ::"n"(N)); }

// =====================================================================
// Generic GEMM: C[M,1024] = A @ W, 128x128x32 tile, 3-stage cp.async.
// cvt_store: round result to tf32 before storing (for q/k/v producers).
// =====================================================================
#define GS 3
#define SA_ST (128 * 36)
#define SB_ST (32 * 136)
#define G_SMEM (GS * (SA_ST + SB_ST) * 4)

__global__ __launch_bounds__(256) void gemm_tf32(const float* __restrict__ A,
                                                 const float* __restrict__ W,
                                                 float* __restrict__ C, int cvt_store) {
    extern __shared__ float sm[];
    float* sA = sm;
    float* sB = sm + GS * SA_ST;
    const int tid = threadIdx.x;
    const int m0 = blockIdx.y * 128, n0 = blockIdx.x * 128;
    const int w = tid >> 5, lane = tid & 31, g = lane >> 2, tg = lane & 3;
    const int wm = (w >> 2) * 64, wn = (w & 3) * 32;

    float acc[4][4][4]{};

    auto load_tile = [&](int st, int kt) {
        float* a = sA + st * SA_ST;
        float* b = sB + st * SB_ST;
#pragma unroll
        for (int i = 0; i < 4; i++) {
            int c = tid + 256 * i;
            int r = c >> 3, cc = (c & 7) * 4;
            cpa16(a + r * 36 + cc, A + (size_t)(m0 + r) * DIM + kt + cc);
        }
#pragma unroll
        for (int i = 0; i < 4; i++) {
            int c = tid + 256 * i;
            int r = c >> 5, cc = (c & 31) * 4;
            cpa16(b + r * 136 + cc, W + (size_t)(kt + r) * DIM + n0 + cc);
        }
    };

    const int NK = DIM / 32;
#pragma unroll
    for (int s = 0; s < GS - 1; s++) {
        load_tile(s, s * 32);
        cp_commit();
    }
    for (int t = 0; t < NK; t++) {
        cp_wait<GS - 2>();
        __syncthreads();
        int ld = t + GS - 1;
        if (ld < NK) load_tile(ld % GS, ld * 32);
        cp_commit();
        const float* a = sA + (t % GS) * SA_ST;
        const float* b = sB + (t % GS) * SB_ST;
#pragma unroll
        for (int kk = 0; kk < 32; kk += 8) {
            uint32_t af[4][4], bf[4][2];
#pragma unroll
            for (int mt = 0; mt < 4; mt++) {
                int r = wm + mt * 16;
                af[mt][0] = f2tf(a[(r + g) * 36 + kk + tg]);
                af[mt][1] = f2tf(a[(r + g + 8) * 36 + kk + tg]);
                af[mt][2] = f2tf(a[(r + g) * 36 + kk + tg + 4]);
                af[mt][3] = f2tf(a[(r + g + 8) * 36 + kk + tg + 4]);
            }
#pragma unroll
            for (int nt = 0; nt < 4; nt++) {
                int nb = wn + nt * 8;
                bf[nt][0] = f2tf(b[(kk + tg) * 136 + nb + g]);
                bf[nt][1] = f2tf(b[(kk + tg + 4) * 136 + nb + g]);
            }
#pragma unroll
            for (int mt = 0; mt < 4; mt++)
#pragma unroll
                for (int nt = 0; nt < 4; nt++) mma8(acc[mt][nt], af[mt], bf[nt]);
        }
    }
#pragma unroll
    for (int mt = 0; mt < 4; mt++)
#pragma unroll
        for (int nt = 0; nt < 4; nt++) {
            int row = m0 + wm + mt * 16 + g;
            int col = n0 + wn + nt * 8 + 2 * tg;
            float e[4];
#pragma unroll
            for (int i = 0; i < 4; i++)
                e[i] = cvt_store ? __uint_as_float(f2tf(acc[mt][nt][i])) : acc[mt][nt][i];
            *(float2*)(C + (size_t)row * DIM + col) = make_float2(e[0], e[1]);
            *(float2*)(C + (size_t)(row + 8) * DIM + col) = make_float2(e[2], e[3]);
        }
}

// =====================================================================
// Pass A: R[b,q,k] = 1 / sum_h exp(scale * q_h . k_h)
// Per-head 128x64 Q,K tiles, 2-stage double buffer over heads.
// =====================================================================
#define ZT_ST (128 * 68)
#define Z_SMEM (4 * ZT_ST * 4)

__global__ __launch_bounds__(256) void attn_z() {
    extern __shared__ float sm[];
    float* sQ = sm;              // [2][128*68]
    float* sK = sm + 2 * ZT_ST;  // [2][128*68]
    const int tid = threadIdx.x;
    const int b = blockIdx.z, qt = blockIdx.y * 128, kt = blockIdx.x * 128;
    const int w = tid >> 5, lane = tid & 31, g = lane >> 2, tg = lane & 3;
    const int wm = (w >> 2) * 64, wn = (w & 3) * 32;

    const float* qb = g_q + (size_t)(b * SEQ + qt) * DIM;
    const float* kb = g_k + (size_t)(b * SEQ + kt) * DIM;

    auto load_head = [&](int st, int h) {
        float* q = sQ + st * ZT_ST;
        float* k = sK + st * ZT_ST;
#pragma unroll
        for (int i = 0; i < 8; i++) {
            int c = tid + 256 * i;
            int r = c >> 4, cc = (c & 15) * 4;
            cpa16(q + r * 68 + cc, qb + (size_t)r * DIM + h * HD + cc);
            cpa16(k + r * 68 + cc, kb + (size_t)r * DIM + h * HD + cc);
        }
    };

    float zacc[4][4][4]{};
    load_head(0, 0);
    cp_commit();

    for (int h = 0; h < NH; h++) {
        cp_wait<0>();
        __syncthreads();
        if (h + 1 < NH) load_head((h + 1) & 1, h + 1);
        cp_commit();
        const float* q = sQ + (h & 1) * ZT_ST;
        const float* k = sK + (h & 1) * ZT_ST;

        float sacc[4][4][4]{};
#pragma unroll
        for (int kk = 0; kk < 64; kk += 8) {
            uint32_t af[4][4], bf[4][2];
#pragma unroll
            for (int mt = 0; mt < 4; mt++) {
                int r = wm + mt * 16;
                af[mt][0] = ldbits(q + (r + g) * 68 + kk + tg);
                af[mt][1] = ldbits(q + (r + g + 8) * 68 + kk + tg);
                af[mt][2] = ldbits(q + (r + g) * 68 + kk + tg + 4);
                af[mt][3] = ldbits(q + (r + g + 8) * 68 + kk + tg + 4);
            }
#pragma unroll
            for (int nt = 0; nt < 4; nt++) {
                int nb = wn + nt * 8;
                bf[nt][0] = ldbits(k + (nb + g) * 68 + kk + tg);
                bf[nt][1] = ldbits(k + (nb + g) * 68 + kk + tg + 4);
            }
#pragma unroll
            for (int mt = 0; mt < 4; mt++)
#pragma unroll
                for (int nt = 0; nt < 4; nt++) mma8(sacc[mt][nt], af[mt], bf[nt]);
        }
#pragma unroll
        for (int i = 0; i < 4; i++)
#pragma unroll
            for (int j = 0; j < 4; j++)
#pragma unroll
                for (int e = 0; e < 4; e++) zacc[i][j][e] += __expf(sacc[i][j][e] * SCALE);
    }
#pragma unroll
    for (int mt = 0; mt < 4; mt++)
#pragma unroll
        for (int nt = 0; nt < 4; nt++) {
            int row = qt + wm + mt * 16 + g;
            int col = kt + wn + nt * 8 + 2 * tg;
            float* rp = g_r + ((size_t)b * SEQ + row) * SEQ + col;
            *(float2*)rp = make_float2(1.f / zacc[mt][nt][0], 1.f / zacc[mt][nt][1]);
            *(float2*)(rp + (size_t)8 * SEQ) = make_float2(1.f / zacc[mt][nt][2], 1.f / zacc[mt][nt][3]);
        }
}

// =====================================================================
// Pass B: ctx = sum_k exp(scale*S)*R * V  per (b,h,qtile).
// K double-buffered, V prefetched during GEMM1, R prefetched into sP.
// =====================================================================
#define CQ_ST (128 * 68)
#define CV_ST (128 * 72)
#define CP_ST (128 * 132)
#define C_SMEM ((3 * CQ_ST + CV_ST + CP_ST) * 4)

__global__ __launch_bounds__(256) void attn_ctx() {
    extern __shared__ float sm[];
    float* sQ = sm;
    float* sK = sm + CQ_ST;  // [2]
    float* sV = sm + 3 * CQ_ST;
    float* sP = sV + CV_ST;

    const int tid = threadIdx.x;
    const int b = blockIdx.z, h = blockIdx.y, qt = blockIdx.x * 128;
    const int w = tid >> 5, lane = tid & 31, g = lane >> 2, tg = lane & 3;
    const int wm = (w >> 2) * 64, wn = (w & 3) * 32;
    const int wn2 = (w & 3) * 16;

    const float* qb = g_q + (size_t)(b * SEQ + qt) * DIM + h * HD;
    // prologue: Q + K(0) in one group
#pragma unroll
    for (int i = 0; i < 8; i++) {
        int c = tid + 256 * i;
        int r = c >> 4, cc = (c & 15) * 4;
        cpa16(sQ + r * 68 + cc, qb + (size_t)r * DIM + cc);
    }
    {
        const float* kb = g_k + (size_t)(b * SEQ) * DIM + h * HD;
#pragma unroll
        for (int i = 0; i < 8; i++) {
            int c = tid + 256 * i;
            int r = c >> 4, cc = (c & 15) * 4;
            cpa16(sK + r * 68 + cc, kb + (size_t)r * DIM + cc);
        }
    }
    cp_commit();

    float cacc[4][2][4]{};

    for (int t = 0; t < SEQ / 128; t++) {
        const int kt = t * 128;
        // issue V(t) and R(t)
        {
            const float* vb = g_v + (size_t)(b * SEQ + kt) * DIM + h * HD;
#pragma unroll
            for (int i = 0; i < 8; i++) {
                int c = tid + 256 * i;
                int r = c >> 4, cc = (c & 15) * 4;
                cpa16(sV + r * 72 + cc, vb + (size_t)r * DIM + cc);
            }
            const float* rb = g_r + ((size_t)b * SEQ + qt) * SEQ + kt;
#pragma unroll
            for (int i = 0; i < 16; i++) {
                int c = tid + 256 * i;
                int r = c >> 5, cc = (c & 31) * 4;
                cpa16(sP + r * 132 + cc, rb + (size_t)r * SEQ + cc);
            }
        }
        cp_commit();
        cp_wait<1>();  // K(t) (and Q) ready
        __syncthreads();

        // issue K(t+1)
        {
            int ktn = (t + 1 < SEQ / 128) ? kt + 128 : 0;
            const float* kb = g_k + (size_t)(b * SEQ + ktn) * DIM + h * HD;
            float* kd = sK + ((t + 1) & 1) * CQ_ST;
#pragma unroll
            for (int i = 0; i < 8; i++) {
                int c = tid + 256 * i;
                int r = c >> 4, cc = (c & 15) * 4;
                cpa16(kd + r * 68 + cc, kb + (size_t)r * DIM + cc);
            }
        }
        cp_commit();

        // GEMM1: S = Q @ K^T (128x128x64)
        const float* kc = sK + (t & 1) * CQ_ST;
        float sacc[4][4][4]{};
#pragma unroll
        for (int kk = 0; kk < 64; kk += 8) {
            uint32_t af[4][4], bf[4][2];
#pragma unroll
            for (int mt = 0; mt < 4; mt++) {
                int r = wm + mt * 16;
                af[mt][0] = ldbits(sQ + (r + g) * 68 + kk + tg);
                af[mt][1] = ldbits(sQ + (r + g + 8) * 68 + kk + tg);
                af[mt][2] = ldbits(sQ + (r + g) * 68 + kk + tg + 4);
                af[mt][3] = ldbits(sQ + (r + g + 8) * 68 + kk + tg + 4);
            }
#pragma unroll
            for (int nt = 0; nt < 4; nt++) {
                int nb = wn + nt * 8;
                bf[nt][0] = ldbits(kc + (nb + g) * 68 + kk + tg);
                bf[nt][1] = ldbits(kc + (nb + g) * 68 + kk + tg + 4);
            }
#pragma unroll
            for (int mt = 0; mt < 4; mt++)
#pragma unroll
                for (int nt = 0; nt < 4; nt++) mma8(sacc[mt][nt], af[mt], bf[nt]);
        }

        cp_wait<1>();  // V(t), R(t) ready (K(t+1) may pend)
        __syncthreads();

        // P = tf32(exp(scale*S) * R), in-place in sP
#pragma unroll
        for (int mt = 0; mt < 4; mt++)
#pragma unroll
            for (int nt = 0; nt < 4; nt++) {
                int row = wm + mt * 16 + g;
                int col = wn + nt * 8 + 2 * tg;
                float* p0 = sP + row * 132 + col;
                float* p1 = sP + (row + 8) * 132 + col;
                float r00 = p0[0], r01 = p0[1], r10 = p1[0], r11 = p1[1];
                p0[0] = __uint_as_float(f2tf(__expf(sacc[mt][nt][0] * SCALE) * r00));
                p0[1] = __uint_as_float(f2tf(__expf(sacc[mt][nt][1] * SCALE) * r01));
                p1[0] = __uint_as_float(f2tf(__expf(sacc[mt][nt][2] * SCALE) * r10));
                p1[1] = __uint_as_float(f2tf(__expf(sacc[mt][nt][3] * SCALE) * r11));
            }
        __syncthreads();

        // GEMM2: ctx += P @ V (128x64x128)
#pragma unroll
        for (int kk = 0; kk < 128; kk += 8) {
            uint32_t af[4][4], bf[2][2];
#pragma unroll
            for (int mt = 0; mt < 4; mt++) {
                int r = wm + mt * 16;
                af[mt][0] = ldbits(sP + (r + g) * 132 + kk + tg);
                af[mt][1] = ldbits(sP + (r + g + 8) * 132 + kk + tg);
                af[mt][2] = ldbits(sP + (r + g) * 132 + kk + tg + 4);
                af[mt][3] = ldbits(sP + (r + g + 8) * 132 + kk + tg + 4);
            }
#pragma unroll
            for (int nt = 0; nt < 2; nt++) {
                int nb = wn2 + nt * 8;
                bf[nt][0] = ldbits(sV + (kk + tg) * 72 + nb + g);
                bf[nt][1] = ldbits(sV + (kk + tg + 4) * 72 + nb + g);
            }
#pragma unroll
            for (int mt = 0; mt < 4; mt++)
#pragma unroll
                for (int nt = 0; nt < 2; nt++) mma8(cacc[mt][nt], af[mt], bf[nt]);
        }
        __syncthreads();
    }

    float* cb = g_ctx + (size_t)(b * SEQ + qt) * DIM + h * HD;
#pragma unroll
    for (int mt = 0; mt < 4; mt++)
#pragma unroll
        for (int nt = 0; nt < 2; nt++) {
            int row = wm + mt * 16 + g;
            int col = wn2 + nt * 8 + 2 * tg;
            *(float2*)(cb + (size_t)row * DIM + col) =
                make_float2(__uint_as_float(f2tf(cacc[mt][nt][0])), __uint_as_float(f2tf(cacc[mt][nt][1])));
            *(float2*)(cb + (size_t)(row + 8) * DIM + col) =
                make_float2(__uint_as_float(f2tf(cacc[mt][nt][2])), __uint_as_float(f2tf(cacc[mt][nt][3])));
        }
}

// =====================================================================
extern "C" void kernel_launch(void* const* d_in, const int* in_sizes, int n_in,
                              void* d_out, int out_size) {
    const float* x = (const float*)d_in[0];
    const float* wq = (const float*)d_in[1];
    const float* wk = (const float*)d_in[2];
    const float* wv = (const float*)d_in[3];
    const float* wo = (const float*)d_in[4];
    float* out = (float*)d_out;

    float *q, *k, *v, *ctx;
    cudaGetSymbolAddress((void**)&q, g_q);
    cudaGetSymbolAddress((void**)&k, g_k);
    cudaGetSymbolAddress((void**)&v, g_v);
    cudaGetSymbolAddress((void**)&ctx, g_ctx);

    static int attr_done = 0;
    if (!attr_done) {
        cudaFuncSetAttribute(gemm_tf32, cudaFuncAttributeMaxDynamicSharedMemorySize, G_SMEM);
        cudaFuncSetAttribute(attn_z, cudaFuncAttributeMaxDynamicSharedMemorySize, Z_SMEM);
        cudaFuncSetAttribute(attn_ctx, cudaFuncAttributeMaxDynamicSharedMemorySize, C_SMEM);
        attr_done = 1;
    }

    dim3 gg(DIM / 128, MTOT / 128);  // (8, 64)
    gemm_tf32<<<gg, 256, G_SMEM>>>(x, wq, q, 1);
    gemm_tf32<<<gg, 256, G_SMEM>>>(x, wk, k, 1);
    gemm_tf32<<<gg, 256, G_SMEM>>>(x, wv, v, 1);

    attn_z<<<dim3(SEQ / 128, SEQ / 128, BATCH), 256, Z_SMEM>>>();

    attn_ctx<<<dim3(SEQ / 128, NH, BATCH), 256, C_SMEM>>>();

    gemm_tf32<<<gg, 256, G_SMEM>>>(ctx, wo, out, 0);
}

// round 3
// speedup vs baseline: 1.1642x; 1.1642x over previous
#include <cuda_runtime.h>
#include <stdint.h>

#define BATCH 4
#define SEQ   2048
#define DIM   1024
#define NH    16
#define HD    64
#define SCALE 0.125f
#define MTOT  (BATCH*SEQ)

// ---- scratch ----
__device__ float g_q[MTOT * DIM];
__device__ float g_k[MTOT * DIM];
__device__ float g_v[MTOT * DIM];
__device__ float g_ctx[MTOT * DIM];
__device__ float g_r[(size_t)BATCH * SEQ * SEQ];  // 1/Z
__device__ float g_x[MTOT * DIM];                 // tf32-rounded x
__device__ float g_w[4 * DIM * DIM];              // tf32-rounded weights

// ---- helpers ----
__device__ __forceinline__ uint32_t f2tf(float x) {
    uint32_t u;
    asm("cvt.rna.tf32.f32 %0, %1;" : "=r"(u) : "f"(x));
    return u;
}
__device__ __forceinline__ uint32_t ldbits(const float* p) { return __float_as_uint(*p); }

__device__ __forceinline__ void mma8(float c[4], const uint32_t a[4], const uint32_t b[2]) {
    asm volatile(
        "mma.sync.aligned.m16n8k8.row.col.f32.tf32.tf32.f32 "
        "{%0,%1,%2,%3}, {%4,%5,%6,%7}, {%8,%9}, {%0,%1,%2,%3};\n"
        : "+f"(c[0]), "+f"(c[1]), "+f"(c[2]), "+f"(c[3])
        : "r"(a[0]), "r"(a[1]), "r"(a[2]), "r"(a[3]), "r"(b[0]), "r"(b[1]));
}
__device__ __forceinline__ void cpa16(float* s, const float* g) {
    uint32_t sa = (uint32_t)__cvta_generic_to_shared(s);
    asm volatile("cp.async.ca.shared.global [%0], [%1], 16;\n" ::"r"(sa), "l"(g));
}
__device__ __forceinline__ void cp_commit() { asm volatile("cp.async.commit_group;\n"); }
template <int N>
__device__ __forceinline__ void cp_wait() { asm volatile("cp.async.wait_group %0;\n" ::"n"(N)); }

// =====================================================================
// Elementwise tf32 rounding (producer-side cvt; removes cvt from GEMMs)
// =====================================================================
__global__ void round_tf32(const float* __restrict__ in, float* __restrict__ out, int n4) {
    int i = blockIdx.x * blockDim.x + threadIdx.x;
    int stride = gridDim.x * blockDim.x;
    for (; i < n4; i += stride) {
        float4 v = ((const float4*)in)[i];
        v.x = __uint_as_float(f2tf(v.x));
        v.y = __uint_as_float(f2tf(v.y));
        v.z = __uint_as_float(f2tf(v.z));
        v.w = __uint_as_float(f2tf(v.w));
        ((float4*)out)[i] = v;
    }
}

// =====================================================================
// GEMM: C[M,1024] = A @ W.  Block 128x256x32, 8 warps (2m x 4n), warp 64x64.
// Inputs MUST be pre-rounded tf32. 3-stage cp.async pipeline.
// =====================================================================
#define GS 3
#define SA_ST (128 * 36)
#define SB_ST (32 * 264)
#define G_SMEM (GS * (SA_ST + SB_ST) * 4)

__global__ __launch_bounds__(256) void gemm_tf32(const float* __restrict__ A,
                                                 const float* __restrict__ W,
                                                 float* __restrict__ C, int cvt_store) {
    extern __shared__ float sm[];
    float* sA = sm;
    float* sB = sm + GS * SA_ST;
    const int tid = threadIdx.x;
    const int m0 = blockIdx.y * 128, n0 = blockIdx.x * 256;
    const int w = tid >> 5, lane = tid & 31, g = lane >> 2, tg = lane & 3;
    const int wm = (w >> 2) * 64, wn = (w & 3) * 64;

    float acc[4][8][4]{};

    auto load_tile = [&](int st, int kt) {
        float* a = sA + st * SA_ST;
        float* b = sB + st * SB_ST;
#pragma unroll
        for (int i = 0; i < 4; i++) {
            int c = tid + 256 * i;
            int r = c >> 3, cc = (c & 7) * 4;
            cpa16(a + r * 36 + cc, A + (size_t)(m0 + r) * DIM + kt + cc);
        }
#pragma unroll
        for (int i = 0; i < 8; i++) {
            int c = tid + 256 * i;
            int r = c >> 6, cc = (c & 63) * 4;
            cpa16(b + r * 264 + cc, W + (size_t)(kt + r) * DIM + n0 + cc);
        }
    };

    const int NK = DIM / 32;
#pragma unroll
    for (int s = 0; s < GS - 1; s++) {
        load_tile(s, s * 32);
        cp_commit();
    }
    for (int t = 0; t < NK; t++) {
        cp_wait<GS - 2>();
        __syncthreads();
        int ld = t + GS - 1;
        if (ld < NK) load_tile(ld % GS, ld * 32);
        cp_commit();
        const float* a = sA + (t % GS) * SA_ST;
        const float* b = sB + (t % GS) * SB_ST;
#pragma unroll
        for (int kk = 0; kk < 32; kk += 8) {
            uint32_t af[4][4], bf[8][2];
#pragma unroll
            for (int mt = 0; mt < 4; mt++) {
                int r = wm + mt * 16;
                af[mt][0] = ldbits(a + (r + g) * 36 + kk + tg);
                af[mt][1] = ldbits(a + (r + g + 8) * 36 + kk + tg);
                af[mt][2] = ldbits(a + (r + g) * 36 + kk + tg + 4);
                af[mt][3] = ldbits(a + (r + g + 8) * 36 + kk + tg + 4);
            }
#pragma unroll
            for (int nt = 0; nt < 8; nt++) {
                int nb = wn + nt * 8;
                bf[nt][0] = ldbits(b + (kk + tg) * 264 + nb + g);
                bf[nt][1] = ldbits(b + (kk + tg + 4) * 264 + nb + g);
            }
#pragma unroll
            for (int mt = 0; mt < 4; mt++)
#pragma unroll
                for (int nt = 0; nt < 8; nt++) mma8(acc[mt][nt], af[mt], bf[nt]);
        }
    }
#pragma unroll
    for (int mt = 0; mt < 4; mt++)
#pragma unroll
        for (int nt = 0; nt < 8; nt++) {
            int row = m0 + wm + mt * 16 + g;
            int col = n0 + wn + nt * 8 + 2 * tg;
            float e[4];
#pragma unroll
            for (int i = 0; i < 4; i++)
                e[i] = cvt_store ? __uint_as_float(f2tf(acc[mt][nt][i])) : acc[mt][nt][i];
            *(float2*)(C + (size_t)row * DIM + col) = make_float2(e[0], e[1]);
            *(float2*)(C + (size_t)(row + 8) * DIM + col) = make_float2(e[2], e[3]);
        }
}

// =====================================================================
// Pass A: R[b,q,k] = 1 / sum_h exp(scale * q_h . k_h)
// 128x128 tile, per-head double buffer. (64x32 warp tiles: reg ceiling.)
// =====================================================================
#define ZT_ST (128 * 68)
#define Z_SMEM (4 * ZT_ST * 4)

__global__ __launch_bounds__(256) void attn_z() {
    extern __shared__ float sm[];
    float* sQ = sm;
    float* sK = sm + 2 * ZT_ST;
    const int tid = threadIdx.x;
    const int b = blockIdx.z, qt = blockIdx.y * 128, kt = blockIdx.x * 128;
    const int w = tid >> 5, lane = tid & 31, g = lane >> 2, tg = lane & 3;
    const int wm = (w >> 2) * 64, wn = (w & 3) * 32;

    const float* qb = g_q + (size_t)(b * SEQ + qt) * DIM;
    const float* kb = g_k + (size_t)(b * SEQ + kt) * DIM;

    auto load_head = [&](int st, int h) {
        float* q = sQ + st * ZT_ST;
        float* k = sK + st * ZT_ST;
#pragma unroll
        for (int i = 0; i < 8; i++) {
            int c = tid + 256 * i;
            int r = c >> 4, cc = (c & 15) * 4;
            cpa16(q + r * 68 + cc, qb + (size_t)r * DIM + h * HD + cc);
            cpa16(k + r * 68 + cc, kb + (size_t)r * DIM + h * HD + cc);
        }
    };

    float zacc[4][4][4]{};
    load_head(0, 0);
    cp_commit();

    for (int h = 0; h < NH; h++) {
        cp_wait<0>();
        __syncthreads();
        if (h + 1 < NH) load_head((h + 1) & 1, h + 1);
        cp_commit();
        const float* q = sQ + (h & 1) * ZT_ST;
        const float* k = sK + (h & 1) * ZT_ST;

        float sacc[4][4][4]{};
#pragma unroll
        for (int kk = 0; kk < 64; kk += 8) {
            uint32_t af[4][4], bf[4][2];
#pragma unroll
            for (int mt = 0; mt < 4; mt++) {
                int r = wm + mt * 16;
                af[mt][0] = ldbits(q + (r + g) * 68 + kk + tg);
                af[mt][1] = ldbits(q + (r + g + 8) * 68 + kk + tg);
                af[mt][2] = ldbits(q + (r + g) * 68 + kk + tg + 4);
                af[mt][3] = ldbits(q + (r + g + 8) * 68 + kk + tg + 4);
            }
#pragma unroll
            for (int nt = 0; nt < 4; nt++) {
                int nb = wn + nt * 8;
                bf[nt][0] = ldbits(k + (nb + g) * 68 + kk + tg);
                bf[nt][1] = ldbits(k + (nb + g) * 68 + kk + tg + 4);
            }
#pragma unroll
            for (int mt = 0; mt < 4; mt++)
#pragma unroll
                for (int nt = 0; nt < 4; nt++) mma8(sacc[mt][nt], af[mt], bf[nt]);
        }
#pragma unroll
        for (int i = 0; i < 4; i++)
#pragma unroll
            for (int j = 0; j < 4; j++)
#pragma unroll
                for (int e = 0; e < 4; e++) zacc[i][j][e] += __expf(sacc[i][j][e] * SCALE);
    }
#pragma unroll
    for (int mt = 0; mt < 4; mt++)
#pragma unroll
        for (int nt = 0; nt < 4; nt++) {
            int row = qt + wm + mt * 16 + g;
            int col = kt + wn + nt * 8 + 2 * tg;
            float* rp = g_r + ((size_t)b * SEQ + row) * SEQ + col;
            *(float2*)rp = make_float2(1.f / zacc[mt][nt][0], 1.f / zacc[mt][nt][1]);
            *(float2*)(rp + (size_t)8 * SEQ) = make_float2(1.f / zacc[mt][nt][2], 1.f / zacc[mt][nt][3]);
        }
}

// =====================================================================
// Pass B: ctx = sum_k exp(scale*S)*R * V  per (b,h,qtile).
// GEMM1: 8 warps 2m x 4n (64x32).  GEMM2: 8 warps 2m x 2n x 2ksplit
// (64x32 over 64-deep half-contraction), reduced once at the end.
// =====================================================================
#define CQ_ST (128 * 68)
#define CV_ST (128 * 72)
#define CP_ST (128 * 132)
#define C_SMEM ((3 * CQ_ST + CV_ST + CP_ST) * 4)

__global__ __launch_bounds__(256) void attn_ctx() {
    extern __shared__ float sm[];
    float* sQ = sm;
    float* sK = sm + CQ_ST;  // [2]
    float* sV = sm + 3 * CQ_ST;
    float* sP = sV + CV_ST;

    const int tid = threadIdx.x;
    const int b = blockIdx.z, h = blockIdx.y, qt = blockIdx.x * 128;
    const int w = tid >> 5, lane = tid & 31, g = lane >> 2, tg = lane & 3;
    const int wm = (w >> 2) * 64, wn = (w & 3) * 32;
    const int wk2 = (w >> 1) & 1, wn2 = (w & 1) * 32;  // GEMM2 k-split / n

    const float* qb = g_q + (size_t)(b * SEQ + qt) * DIM + h * HD;
#pragma unroll
    for (int i = 0; i < 8; i++) {
        int c = tid + 256 * i;
        int r = c >> 4, cc = (c & 15) * 4;
        cpa16(sQ + r * 68 + cc, qb + (size_t)r * DIM + cc);
    }
    {
        const float* kb = g_k + (size_t)(b * SEQ) * DIM + h * HD;
#pragma unroll
        for (int i = 0; i < 8; i++) {
            int c = tid + 256 * i;
            int r = c >> 4, cc = (c & 15) * 4;
            cpa16(sK + r * 68 + cc, kb + (size_t)r * DIM + cc);
        }
    }
    cp_commit();

    float cacc[4][4][4]{};  // GEMM2 partials: 4 m-tiles x 4 n-tiles (64x32)

    for (int t = 0; t < SEQ / 128; t++) {
        const int kt = t * 128;
        {
            const float* vb = g_v + (size_t)(b * SEQ + kt) * DIM + h * HD;
#pragma unroll
            for (int i = 0; i < 8; i++) {
                int c = tid + 256 * i;
                int r = c >> 4, cc = (c & 15) * 4;
                cpa16(sV + r * 72 + cc, vb + (size_t)r * DIM + cc);
            }
            const float* rb = g_r + ((size_t)b * SEQ + qt) * SEQ + kt;
#pragma unroll
            for (int i = 0; i < 16; i++) {
                int c = tid + 256 * i;
                int r = c >> 5, cc = (c & 31) * 4;
                cpa16(sP + r * 132 + cc, rb + (size_t)r * SEQ + cc);
            }
        }
        cp_commit();
        cp_wait<1>();  // K(t) (and Q) ready
        __syncthreads();

        {
            int ktn = (t + 1 < SEQ / 128) ? kt + 128 : 0;
            const float* kb = g_k + (size_t)(b * SEQ + ktn) * DIM + h * HD;
            float* kd = sK + ((t + 1) & 1) * CQ_ST;
#pragma unroll
            for (int i = 0; i < 8; i++) {
                int c = tid + 256 * i;
                int r = c >> 4, cc = (c & 15) * 4;
                cpa16(kd + r * 68 + cc, kb + (size_t)r * DIM + cc);
            }
        }
        cp_commit();

        // GEMM1: S = Q @ K^T (128x128x64)
        const float* kc = sK + (t & 1) * CQ_ST;
        float sacc[4][4][4]{};
#pragma unroll
        for (int kk = 0; kk < 64; kk += 8) {
            uint32_t af[4][4], bf[4][2];
#pragma unroll
            for (int mt = 0; mt < 4; mt++) {
                int r = wm + mt * 16;
                af[mt][0] = ldbits(sQ + (r + g) * 68 + kk + tg);
                af[mt][1] = ldbits(sQ + (r + g + 8) * 68 + kk + tg);
                af[mt][2] = ldbits(sQ + (r + g) * 68 + kk + tg + 4);
                af[mt][3] = ldbits(sQ + (r + g + 8) * 68 + kk + tg + 4);
            }
#pragma unroll
            for (int nt = 0; nt < 4; nt++) {
                int nb = wn + nt * 8;
                bf[nt][0] = ldbits(kc + (nb + g) * 68 + kk + tg);
                bf[nt][1] = ldbits(kc + (nb + g) * 68 + kk + tg + 4);
            }
#pragma unroll
            for (int mt = 0; mt < 4; mt++)
#pragma unroll
                for (int nt = 0; nt < 4; nt++) mma8(sacc[mt][nt], af[mt], bf[nt]);
        }

        cp_wait<1>();  // V(t), R(t) ready
        __syncthreads();

        // P = tf32(exp(scale*S) * R), in-place in sP
#pragma unroll
        for (int mt = 0; mt < 4; mt++)
#pragma unroll
            for (int nt = 0; nt < 4; nt++) {
                int row = wm + mt * 16 + g;
                int col = wn + nt * 8 + 2 * tg;
                float2* p0 = (float2*)(sP + row * 132 + col);
                float2* p1 = (float2*)(sP + (row + 8) * 132 + col);
                float2 r0 = *p0, r1 = *p1;
                *p0 = make_float2(__uint_as_float(f2tf(__expf(sacc[mt][nt][0] * SCALE) * r0.x)),
                                  __uint_as_float(f2tf(__expf(sacc[mt][nt][1] * SCALE) * r0.y)));
                *p1 = make_float2(__uint_as_float(f2tf(__expf(sacc[mt][nt][2] * SCALE) * r1.x)),
                                  __uint_as_float(f2tf(__expf(sacc[mt][nt][3] * SCALE) * r1.y)));
            }
        __syncthreads();

        // GEMM2: ctx += P @ V  (128x64x128, k-split over warps)
#pragma unroll
        for (int kk = 0; kk < 64; kk += 8) {
            const int kx = wk2 * 64 + kk;
            uint32_t af[4][4], bf[4][2];
#pragma unroll
            for (int mt = 0; mt < 4; mt++) {
                int r = wm + mt * 16;
                af[mt][0] = ldbits(sP + (r + g) * 132 + kx + tg);
                af[mt][1] = ldbits(sP + (r + g + 8) * 132 + kx + tg);
                af[mt][2] = ldbits(sP + (r + g) * 132 + kx + tg + 4);
                af[mt][3] = ldbits(sP + (r + g + 8) * 132 + kx + tg + 4);
            }
#pragma unroll
            for (int nt = 0; nt < 4; nt++) {
                int nb = wn2 + nt * 8;
                bf[nt][0] = ldbits(sV + (kx + tg) * 72 + nb + g);
                bf[nt][1] = ldbits(sV + (kx + tg + 4) * 72 + nb + g);
            }
#pragma unroll
            for (int mt = 0; mt < 4; mt++)
#pragma unroll
                for (int nt = 0; nt < 4; nt++) mma8(cacc[mt][nt], af[mt], bf[nt]);
        }
        __syncthreads();
    }

    // reduce k-split partials: wk2==1 warps stage into sP, wk2==0 add + store
    if (wk2 == 1) {
#pragma unroll
        for (int mt = 0; mt < 4; mt++)
#pragma unroll
            for (int nt = 0; nt < 4; nt++) {
                int row = wm + mt * 16 + g;
                int col = wn2 + nt * 8 + 2 * tg;
                *(float2*)(sP + row * 132 + col) = make_float2(cacc[mt][nt][0], cacc[mt][nt][1]);
                *(float2*)(sP + (row + 8) * 132 + col) = make_float2(cacc[mt][nt][2], cacc[mt][nt][3]);
            }
    }
    __syncthreads();
    if (wk2 == 0) {
        float* cb = g_ctx + (size_t)(b * SEQ + qt) * DIM + h * HD;
#pragma unroll
        for (int mt = 0; mt < 4; mt++)
#pragma unroll
            for (int nt = 0; nt < 4; nt++) {
                int row = wm + mt * 16 + g;
                int col = wn2 + nt * 8 + 2 * tg;
                float2 o0 = *(float2*)(sP + row * 132 + col);
                float2 o1 = *(float2*)(sP + (row + 8) * 132 + col);
                o0.x += cacc[mt][nt][0];
                o0.y += cacc[mt][nt][1];
                o1.x += cacc[mt][nt][2];
                o1.y += cacc[mt][nt][3];
                *(float2*)(cb + (size_t)row * DIM + col) =
                    make_float2(__uint_as_float(f2tf(o0.x)), __uint_as_float(f2tf(o0.y)));
                *(float2*)(cb + (size_t)(row + 8) * DIM + col) =
                    make_float2(__uint_as_float(f2tf(o1.x)), __uint_as_float(f2tf(o1.y)));
            }
    }
}

// =====================================================================
extern "C" void kernel_launch(void* const* d_in, const int* in_sizes, int n_in,
                              void* d_out, int out_size) {
    const float* x = (const float*)d_in[0];
    const float* wq = (const float*)d_in[1];
    const float* wk = (const float*)d_in[2];
    const float* wv = (const float*)d_in[3];
    const float* wo = (const float*)d_in[4];
    float* out = (float*)d_out;

    float *q, *k, *v, *ctx, *xr, *wr;
    cudaGetSymbolAddress((void**)&q, g_q);
    cudaGetSymbolAddress((void**)&k, g_k);
    cudaGetSymbolAddress((void**)&v, g_v);
    cudaGetSymbolAddress((void**)&ctx, g_ctx);
    cudaGetSymbolAddress((void**)&xr, g_x);
    cudaGetSymbolAddress((void**)&wr, g_w);

    static int attr_done = 0;
    if (!attr_done) {
        cudaFuncSetAttribute(gemm_tf32, cudaFuncAttributeMaxDynamicSharedMemorySize, G_SMEM);
        cudaFuncSetAttribute(attn_z, cudaFuncAttributeMaxDynamicSharedMemorySize, Z_SMEM);
        cudaFuncSetAttribute(attn_ctx, cudaFuncAttributeMaxDynamicSharedMemorySize, C_SMEM);
        attr_done = 1;
    }

    round_tf32<<<2048, 256>>>(x, xr, MTOT * DIM / 4);
    round_tf32<<<512, 256>>>(wq, wr + 0 * DIM * DIM, DIM * DIM / 4);
    round_tf32<<<512, 256>>>(wk, wr + 1 * DIM * DIM, DIM * DIM / 4);
    round_tf32<<<512, 256>>>(wv, wr + 2 * DIM * DIM, DIM * DIM / 4);
    round_tf32<<<512, 256>>>(wo, wr + 3 * DIM * DIM, DIM * DIM / 4);

    dim3 gg(DIM / 256, MTOT / 128);  // (4, 64)
    gemm_tf32<<<gg, 256, G_SMEM>>>(xr, wr + 0 * DIM * DIM, q, 1);
    gemm_tf32<<<gg, 256, G_SMEM>>>(xr, wr + 1 * DIM * DIM, k, 1);
    gemm_tf32<<<gg, 256, G_SMEM>>>(xr, wr + 2 * DIM * DIM, v, 1);

    attn_z<<<dim3(SEQ / 128, SEQ / 128, BATCH), 256, Z_SMEM>>>();

    attn_ctx<<<dim3(SEQ / 128, NH, BATCH), 256, C_SMEM>>>();

    gemm_tf32<<<gg, 256, G_SMEM>>>(ctx, wr + 3 * DIM * DIM, out, 0);
}